// round 5
// baseline (speedup 1.0000x reference)
#include <cuda_runtime.h>
#include <cuda_bf16.h>

#define N_AGT 100000
#define N_CTX 150000
#define NE    500000
#define D     128

// smem strides (floats)
#define WSTR 132          // padded stride for 128-wide rows
#define WS_FLOATS (128 * WSTR)   // 16896
#define BUF_FLOATS (64 * WSTR)   // 8448

// Wt slots in g_wt: 0=dist2 1=c1top 2=c2 3=q 4=c1mid 5=agt 6=lin 7=c1bot
__device__ float g_wt[8 * 128 * 128];
__device__ float g_qc[(size_t)N_AGT * D];
__device__ float g_cc[(size_t)N_CTX * D];
__device__ float g_abase[(size_t)N_AGT * D];

#define FMA2(d, a, b) asm("fma.rn.f32x2 %0, %1, %2, %0;" : "+l"(d) : "l"(a), "l"(b))

// ---------------------------------------------------------------------------
// Weight pre-transpose: g_wt[slot][j*128+k] = src[k*128+j]
// ---------------------------------------------------------------------------
__global__ void transpose_k(const float* __restrict__ src, int slot) {
    int i = blockIdx.x * blockDim.x + threadIdx.x;   // i = k*128 + j
    if (i < 128 * 128) {
        int k = i >> 7, j = i & 127;
        g_wt[slot * 16384 + j * 128 + k] = src[i];
    }
}

// ---------------------------------------------------------------------------
// Tile helpers (256 threads; tx = tid&15 -> cols tx+16c; ty = tid>>4 -> rows ty*4+r)
// ---------------------------------------------------------------------------
__device__ __forceinline__ void load_w_smem(float* Ws, const float* __restrict__ Wt, int tid) {
    // copy 128x128 (row-major, j-major rows of k) into smem with stride WSTR
#pragma unroll
    for (int i = 0; i < 16; i++) {
        int idx4 = tid + i * 256;          // 0..4095
        int flat = idx4 * 4;
        int row = flat >> 7;
        int k = flat & 127;
        *reinterpret_cast<float4*>(&Ws[row * WSTR + k]) =
            *reinterpret_cast<const float4*>(&Wt[flat]);
    }
}

__device__ __forceinline__ void load_rows_smem(float* dst, const float* __restrict__ src,
                                               int base, int nrows, int tid) {
#pragma unroll
    for (int i = 0; i < 8; i++) {
        int idx4 = tid + i * 256;          // 0..2047
        int flat = idx4 * 4;
        int row = flat >> 7;
        int k = flat & 127;
        int gr = base + row;
        if (gr > nrows - 1) gr = nrows - 1;
        *reinterpret_cast<float4*>(&dst[row * WSTR + k]) =
            *reinterpret_cast<const float4*>(&src[(size_t)gr * D + k]);
    }
}

// out[r][c] = sum_k Xs[row][k] * Ws[col][k]   (Ws holds W transposed: [j][k])
__device__ __forceinline__ void gemm_tile(const float* __restrict__ Xs,
                                          const float* __restrict__ Ws,
                                          int tx, int ty, float out[4][8]) {
    unsigned long long acc[4][8];
#pragma unroll
    for (int r = 0; r < 4; r++)
#pragma unroll
        for (int c = 0; c < 8; c++) acc[r][c] = 0ull;

    const float* xb = Xs + (ty * 4) * WSTR;
    const float* wb = Ws + tx * WSTR;

#pragma unroll 4
    for (int k = 0; k < 128; k += 4) {
        ulonglong2 xv[4];
#pragma unroll
        for (int r = 0; r < 4; r++)
            xv[r] = *reinterpret_cast<const ulonglong2*>(xb + r * WSTR + k);
#pragma unroll
        for (int c = 0; c < 8; c++) {
            ulonglong2 wv = *reinterpret_cast<const ulonglong2*>(wb + (16 * c) * WSTR + k);
#pragma unroll
            for (int r = 0; r < 4; r++) {
                FMA2(acc[r][c], xv[r].x, wv.x);
                FMA2(acc[r][c], xv[r].y, wv.y);
            }
        }
    }
#pragma unroll
    for (int r = 0; r < 4; r++)
#pragma unroll
        for (int c = 0; c < 8; c++) {
            float lo = __uint_as_float((unsigned)(acc[r][c] & 0xFFFFFFFFull));
            float hi = __uint_as_float((unsigned)(acc[r][c] >> 32));
            out[r][c] = lo + hi;
        }
}

__device__ __forceinline__ void gn_rows(float v[4][8], const float gg[8], const float bb[8],
                                        bool do_relu) {
#pragma unroll
    for (int r = 0; r < 4; r++) {
        float s = 0.f, q = 0.f;
#pragma unroll
        for (int c = 0; c < 8; c++) { s += v[r][c]; q += v[r][c] * v[r][c]; }
#pragma unroll
        for (int off = 1; off < 16; off <<= 1) {
            s += __shfl_xor_sync(0xFFFFFFFFu, s, off);
            q += __shfl_xor_sync(0xFFFFFFFFu, q, off);
        }
        float mu = s * (1.0f / 128.0f);
        float var = q * (1.0f / 128.0f) - mu * mu;
        float rstd = rsqrtf(fmaxf(var, 0.f) + 1e-5f);
#pragma unroll
        for (int c = 0; c < 8; c++) {
            float t = (v[r][c] - mu) * rstd * gg[c] + bb[c];
            v[r][c] = do_relu ? fmaxf(t, 0.f) : t;
        }
    }
}

__device__ __forceinline__ void store_tile(float* dst, const float v[4][8], int tx, int ty) {
#pragma unroll
    for (int r = 0; r < 4; r++)
#pragma unroll
        for (int c = 0; c < 8; c++)
            dst[(ty * 4 + r) * WSTR + tx + 16 * c] = v[r][c];
}

__device__ __forceinline__ void load_gb(const float* __restrict__ g, const float* __restrict__ b,
                                        int tx, float gg[8], float bb[8]) {
#pragma unroll
    for (int c = 0; c < 8; c++) { gg[c] = g[tx + 16 * c]; bb[c] = b[tx + 16 * c]; }
}

// ---------------------------------------------------------------------------
// Agent kernel: q = relu(gn(agts@W_q)); g_qc = q@W_c1mid; g_abase = agts@W_agt
// ---------------------------------------------------------------------------
__global__ __launch_bounds__(256, 1)
void agent_kernel(const float* __restrict__ agts,
                  const float* __restrict__ gq, const float* __restrict__ bq) {
    extern __shared__ float sm[];
    float* Ws = sm;
    float* A = Ws + WS_FLOATS;
    float* B = A + BUF_FLOATS;
    int tid = threadIdx.x, tx = tid & 15, ty = tid >> 4;
    int base = blockIdx.x * 64;

    load_rows_smem(A, agts, base, N_AGT, tid);
    load_w_smem(Ws, g_wt + 3 * 16384, tid);        // Wt_q
    __syncthreads();

    float v[4][8];
    gemm_tile(A, Ws, tx, ty, v);
    {
        float gg[8], bb[8];
        load_gb(gq, bq, tx, gg, bb);
        gn_rows(v, gg, bb, true);
    }
    store_tile(B, v, tx, ty);
    __syncthreads();

    load_w_smem(Ws, g_wt + 4 * 16384, tid);        // Wt_c1mid
    __syncthreads();
    gemm_tile(B, Ws, tx, ty, v);
#pragma unroll
    for (int r = 0; r < 4; r++) {
        int row = base + ty * 4 + r;
        if (row < N_AGT)
#pragma unroll
            for (int c = 0; c < 8; c++)
                g_qc[(size_t)row * D + tx + 16 * c] = v[r][c];
    }
    __syncthreads();

    load_w_smem(Ws, g_wt + 5 * 16384, tid);        // Wt_agt
    __syncthreads();
    gemm_tile(A, Ws, tx, ty, v);
#pragma unroll
    for (int r = 0; r < 4; r++) {
        int row = base + ty * 4 + r;
        if (row < N_AGT)
#pragma unroll
            for (int c = 0; c < 8; c++)
                g_abase[(size_t)row * D + tx + 16 * c] = v[r][c];
    }
}

// ---------------------------------------------------------------------------
// Ctx kernel: g_cc = ctx @ W_c1bot
// ---------------------------------------------------------------------------
__global__ __launch_bounds__(256, 1)
void ctx_kernel(const float* __restrict__ ctx) {
    extern __shared__ float sm[];
    float* Ws = sm;
    float* A = Ws + WS_FLOATS;
    int tid = threadIdx.x, tx = tid & 15, ty = tid >> 4;
    int base = blockIdx.x * 64;

    load_rows_smem(A, ctx, base, N_CTX, tid);
    load_w_smem(Ws, g_wt + 7 * 16384, tid);        // Wt_c1bot
    __syncthreads();

    float v[4][8];
    gemm_tile(A, Ws, tx, ty, v);
#pragma unroll
    for (int r = 0; r < 4; r++) {
        int row = base + ty * 4 + r;
        if (row < N_CTX)
#pragma unroll
            for (int c = 0; c < 8; c++)
                g_cc[(size_t)row * D + tx + 16 * c] = v[r][c];
    }
}

// ---------------------------------------------------------------------------
// Edge kernel: full per-edge pipeline, atomic scatter into g_abase
// ---------------------------------------------------------------------------
__global__ __launch_bounds__(256, 1)
void edge_kernel(const float* __restrict__ agt_ctrs, const float* __restrict__ ctx_ctrs,
                 const float* __restrict__ W_dist1, const float* __restrict__ b_dist1,
                 const float* __restrict__ g_dist, const float* __restrict__ b_dist,
                 const float* __restrict__ g_c1, const float* __restrict__ b_c1,
                 const int* __restrict__ hi, const int* __restrict__ wi) {
    extern __shared__ float sm[];
    float* Ws = sm;
    float* A = Ws + WS_FLOATS;
    float* B = A + BUF_FLOATS;
    int* s_hi = (int*)(B + BUF_FLOATS);
    int* s_wi = s_hi + 64;
    float* s_dxy = (float*)(s_wi + 64);

    int tid = threadIdx.x, tx = tid & 15, ty = tid >> 4;
    int e0 = blockIdx.x * 64;

    if (tid < 64) {
        int e = e0 + tid;
        if (e > NE - 1) e = NE - 1;
        int h = hi[e], w = wi[e];
        s_hi[tid] = h;
        s_wi[tid] = w;
        s_dxy[2 * tid]     = agt_ctrs[2 * h]     - ctx_ctrs[2 * w];
        s_dxy[2 * tid + 1] = agt_ctrs[2 * h + 1] - ctx_ctrs[2 * w + 1];
    }
    load_w_smem(Ws, g_wt + 0 * 16384, tid);        // Wt_dist2
    __syncthreads();

    // H1 = relu(d2 @ W_dist1 + b_dist1)  ->  A
#pragma unroll
    for (int i = 0; i < 32; i++) {
        int idx = tid + i * 256;
        int row = idx >> 7, col = idx & 127;
        float t = s_dxy[2 * row] * W_dist1[col]
                + s_dxy[2 * row + 1] * W_dist1[128 + col]
                + b_dist1[col];
        A[row * WSTR + col] = fmaxf(t, 0.f);
    }
    __syncthreads();

    float v[4][8];
    // d = relu(gn(H1 @ W_dist2))  ->  B
    gemm_tile(A, Ws, tx, ty, v);
    {
        float gg[8], bb[8];
        load_gb(g_dist, b_dist, tx, gg, bb);
        gn_rows(v, gg, bb, true);
    }
    store_tile(B, v, tx, ty);
    __syncthreads();

    load_w_smem(Ws, g_wt + 1 * 16384, tid);        // Wt_c1top
    __syncthreads();

    // c1 = relu(gn(d @ W_c1top + qc[hi] + cc[wi]))  ->  A
    gemm_tile(B, Ws, tx, ty, v);
#pragma unroll
    for (int r = 0; r < 4; r++) {
        int row = ty * 4 + r;
        size_t h = (size_t)s_hi[row];
        size_t w = (size_t)s_wi[row];
#pragma unroll
        for (int c = 0; c < 8; c++) {
            int col = tx + 16 * c;
            v[r][c] += g_qc[h * D + col] + g_cc[w * D + col];
        }
    }
    {
        float gg[8], bb[8];
        load_gb(g_c1, b_c1, tx, gg, bb);
        gn_rows(v, gg, bb, true);
    }
    store_tile(A, v, tx, ty);
    __syncthreads();

    load_w_smem(Ws, g_wt + 2 * 16384, tid);        // Wt_c2
    __syncthreads();

    // out = c1 @ W_c2 -> atomic scatter to abase[hi]
    gemm_tile(A, Ws, tx, ty, v);
#pragma unroll
    for (int r = 0; r < 4; r++) {
        int row = ty * 4 + r;
        if (e0 + row < NE) {
            size_t h = (size_t)s_hi[row];
#pragma unroll
            for (int c = 0; c < 8; c++)
                atomicAdd(&g_abase[h * D + tx + 16 * c], v[r][c]);
        }
    }
}

// ---------------------------------------------------------------------------
// Final kernel: t = relu(gn(abase)); out = relu(gn(t@W_lin) + agts)
// ---------------------------------------------------------------------------
__global__ __launch_bounds__(256, 1)
void final_kernel(const float* __restrict__ agts,
                  const float* __restrict__ gn_g, const float* __restrict__ gn_b,
                  const float* __restrict__ gl_g, const float* __restrict__ gl_b,
                  float* __restrict__ out) {
    extern __shared__ float sm[];
    float* Ws = sm;
    float* A = Ws + WS_FLOATS;
    int tid = threadIdx.x, tx = tid & 15, ty = tid >> 4;
    int base = blockIdx.x * 64;

    float v[4][8];
#pragma unroll
    for (int r = 0; r < 4; r++) {
        int gr = base + ty * 4 + r;
        if (gr > N_AGT - 1) gr = N_AGT - 1;
#pragma unroll
        for (int c = 0; c < 8; c++)
            v[r][c] = g_abase[(size_t)gr * D + tx + 16 * c];
    }
    {
        float gg[8], bb[8];
        load_gb(gn_g, gn_b, tx, gg, bb);
        gn_rows(v, gg, bb, true);
    }
    store_tile(A, v, tx, ty);
    load_w_smem(Ws, g_wt + 6 * 16384, tid);        // Wt_lin
    __syncthreads();

    gemm_tile(A, Ws, tx, ty, v);
    {
        float gg[8], bb[8];
        load_gb(gl_g, gl_b, tx, gg, bb);
        gn_rows(v, gg, bb, false);
    }
#pragma unroll
    for (int r = 0; r < 4; r++) {
        int row = base + ty * 4 + r;
        if (row < N_AGT) {
#pragma unroll
            for (int c = 0; c < 8; c++) {
                int col = tx + 16 * c;
                float t = v[r][c] + agts[(size_t)row * D + col];
                out[(size_t)row * D + col] = fmaxf(t, 0.f);
            }
        }
    }
}

// ---------------------------------------------------------------------------
// Launch
// ---------------------------------------------------------------------------
extern "C" void kernel_launch(void* const* d_in, const int* in_sizes, int n_in,
                              void* d_out, int out_size) {
    const float* agts     = (const float*)d_in[0];
    const float* ctx      = (const float*)d_in[1];
    const float* agt_ctrs = (const float*)d_in[2];
    const float* ctx_ctrs = (const float*)d_in[3];
    const float* W_dist1  = (const float*)d_in[4];
    const float* b_dist1  = (const float*)d_in[5];
    const float* W_dist2  = (const float*)d_in[6];
    const float* g_dist   = (const float*)d_in[7];
    const float* b_dist   = (const float*)d_in[8];
    const float* W_q      = (const float*)d_in[9];
    const float* g_q      = (const float*)d_in[10];
    const float* b_q      = (const float*)d_in[11];
    const float* W_c1     = (const float*)d_in[12];
    const float* g_c1     = (const float*)d_in[13];
    const float* b_c1     = (const float*)d_in[14];
    const float* W_c2     = (const float*)d_in[15];
    const float* W_agt    = (const float*)d_in[16];
    const float* g_n      = (const float*)d_in[17];
    const float* b_n      = (const float*)d_in[18];
    const float* W_lin    = (const float*)d_in[19];
    const float* g_lin    = (const float*)d_in[20];
    const float* b_lin    = (const float*)d_in[21];
    const int*   hi       = (const int*)d_in[22];
    const int*   wi       = (const int*)d_in[23];
    float* outp = (float*)d_out;

    const int EDGE_SMEM  = (WS_FLOATS + 2 * BUF_FLOATS) * 4 + 64 * 4 * 2 + 128 * 4;
    const int AGENT_SMEM = (WS_FLOATS + 2 * BUF_FLOATS) * 4;
    const int CTX_SMEM   = (WS_FLOATS + BUF_FLOATS) * 4;

    cudaFuncSetAttribute(agent_kernel, cudaFuncAttributeMaxDynamicSharedMemorySize, AGENT_SMEM);
    cudaFuncSetAttribute(ctx_kernel,   cudaFuncAttributeMaxDynamicSharedMemorySize, CTX_SMEM);
    cudaFuncSetAttribute(edge_kernel,  cudaFuncAttributeMaxDynamicSharedMemorySize, EDGE_SMEM);
    cudaFuncSetAttribute(final_kernel, cudaFuncAttributeMaxDynamicSharedMemorySize, CTX_SMEM);

    // 1) transpose all weight matrices once (k contiguous per output column)
    transpose_k<<<64, 256>>>(W_dist2, 0);
    transpose_k<<<64, 256>>>(W_c1 + 0 * 16384, 1);   // c1top (d part)
    transpose_k<<<64, 256>>>(W_c2, 2);
    transpose_k<<<64, 256>>>(W_q, 3);
    transpose_k<<<64, 256>>>(W_c1 + 1 * 16384, 4);   // c1mid (q part)
    transpose_k<<<64, 256>>>(W_agt, 5);
    transpose_k<<<64, 256>>>(W_lin, 6);
    transpose_k<<<64, 256>>>(W_c1 + 2 * 16384, 7);   // c1bot (ctx part)

    // 2) per-node precomputes
    agent_kernel<<<(N_AGT + 63) / 64, 256, AGENT_SMEM>>>(agts, g_q, b_q);
    ctx_kernel<<<(N_CTX + 63) / 64, 256, CTX_SMEM>>>(ctx);

    // 3) per-edge pipeline + scatter
    edge_kernel<<<(NE + 63) / 64, 256, EDGE_SMEM>>>(agt_ctrs, ctx_ctrs,
                                                    W_dist1, b_dist1,
                                                    g_dist, b_dist,
                                                    g_c1, b_c1,
                                                    hi, wi);

    // 4) final norm + linear + residual
    final_kernel<<<(N_AGT + 63) / 64, 256, CTX_SMEM>>>(agts, g_n, b_n, g_lin, b_lin, outp);
}